// round 15
// baseline (speedup 1.0000x reference)
#include <cuda_runtime.h>
#include <math.h>
#include <stdint.h>

#define NB 8
#define LW 512
#define LE 64
#define SS 576
#define HH 1024
#define NHEAD 16
#define HD 64
#define MTOT (NB*SS)      // 4608

typedef unsigned long long u64;

// ---------------- scratch (device globals; no allocation) ----------------
__device__ float g_q  [ (long)MTOT * HH ];
__device__ float g_k  [ (long)MTOT * HH ];
__device__ float g_v  [ (long)MTOT * HH ];
__device__ float g_ctx[ (long)MTOT * HH ];
__device__ float g_y  [ (long)MTOT * HH ];

// ---------------- packed f32x2 helpers ----------------
__device__ __forceinline__ u64 pack2(float lo, float hi) {
    u64 r; asm("mov.b64 %0, {%1, %2};" : "=l"(r) : "f"(lo), "f"(hi)); return r;
}
__device__ __forceinline__ void fma2(u64& d, u64 a, u64 b) {
    asm("fma.rn.f32x2 %0, %1, %2, %0;" : "+l"(d) : "l"(a), "l"(b));
}

__device__ __forceinline__ uint32_t smem_u32(const void* p) {
    uint32_t a;
    asm("{ .reg .u64 t; cvta.to.shared.u64 t, %1; cvt.u32.u64 %0, t; }" : "=r"(a) : "l"(p));
    return a;
}
__device__ __forceinline__ void cp_async16(uint32_t dst, const void* src) {
    asm volatile("cp.async.cg.shared.global [%0], [%1], 16;" :: "r"(dst), "l"(src));
}
#define CP_COMMIT() asm volatile("cp.async.commit_group;" ::: "memory")
#define CP_WAIT1()  asm volatile("cp.async.wait_group 1;" ::: "memory")
#define CP_WAIT0()  asm volatile("cp.async.wait_group 0;" ::: "memory")

// row m of virtual concat([B,Lw,H] word, [B,Le,H] ent)
__device__ __forceinline__ const float* xrow(const float* __restrict__ word,
                                             const float* __restrict__ ent, int m) {
    int b = m / SS, s = m % SS;
    return (s < LW) ? word + ((long)b * LW + s) * HH
                    : ent  + ((long)b * LE + (s - LW)) * HH;
}

// ------------- software-pipelined fp32 GEMM, 16x8 microtile, FFMA2 core -----
// B stored DUPLICATED with chunk swizzle: row = 16 regions x 4 chunks (16B).
// Logical chunk l of region r lives at physical chunk (l + (r>>1)) & 3.
// Reads are conflict-free (audited); no pack2 in the inner loop.
template<bool RESID, bool CONCAT_A>
__global__ __launch_bounds__(128)
void gemm_kernel(const float* __restrict__ Adirect,
                 const float* __restrict__ word,
                 const float* __restrict__ ent,
                 const float* __restrict__ W0,
                 const float* __restrict__ W1,
                 const float* __restrict__ W2,
                 const float* __restrict__ b0,
                 const float* __restrict__ b1,
                 const float* __restrict__ b2,
                 float* __restrict__ C0,
                 float* __restrict__ C1,
                 float* __restrict__ C2) {
    __shared__ float As[2][16][132];
    __shared__ float Bs[2][16][256];   // duplicated, swizzled; 1024B rows

    int z = blockIdx.z;
    const float* W    = (z == 0) ? W0 : (z == 1) ? W1 : W2;
    const float* bias = (z == 0) ? b0 : (z == 1) ? b1 : b2;
    float*       C    = (z == 0) ? C0 : (z == 1) ? C1 : C2;

    int tid = threadIdx.x;
    int bm = blockIdx.y * 128;
    int bn = blockIdx.x * 128;
    int ty = tid >> 4;
    int tx = tid & 15;

    u64 acc2[8][8];
    #pragma unroll
    for (int i = 0; i < 8; i++)
        #pragma unroll
        for (int j = 0; j < 8; j++) acc2[i][j] = 0ULL;

    // A loader
    int arow_b = tid >> 2;
    int acol   = (tid & 3) * 4;
    const float* Aptr[4];
    #pragma unroll
    for (int t = 0; t < 4; t++) {
        int m = bm + arow_b + t * 32;
        Aptr[t] = (CONCAT_A ? xrow(word, ent, m)
                            : Adirect + (long)m * HH) + acol;
    }

    // B loader: idx = tid + 128t; row = idx>>5; lane31 = idx&31 covers orig cols lane31*4..+3
    const float* Wp[4];
    int boff0[4], boff1[4], brow_[4];
    #pragma unroll
    for (int t = 0; t < 4; t++) {
        int idx = tid + t * 128;
        int br = idx >> 5;
        int lane31 = idx & 31;
        brow_[t] = br;
        Wp[t] = W + (long)br * HH + bn + lane31 * 4;
        int region = lane31 >> 1;
        int l0 = (lane31 & 1) * 2;
        int p0 = (l0 + (region >> 1)) & 3;
        int p1 = (l0 + 1 + (region >> 1)) & 3;
        boff0[t] = region * 16 + p0 * 4;   // float offset within row
        boff1[t] = region * 16 + p1 * 4;
    }

    // reader chunk offsets (floats within row), conflict-free swizzle
    int co[4];
    #pragma unroll
    for (int i = 0; i < 4; i++)
        co[i] = tx * 16 + (((i + (tx >> 1)) & 3) * 4);

    auto store_b = [&](int buf, int t, float4 w) {
        float* row = &Bs[buf][brow_[t]][0];
        *(float4*)(row + boff0[t]) = make_float4(w.x, w.x, w.y, w.y);
        *(float4*)(row + boff1[t]) = make_float4(w.z, w.z, w.w, w.w);
    };

    // ---- prologue: stage tile 0 ----
    {
        #pragma unroll
        for (int t = 0; t < 4; t++) {
            float4 a = *(const float4*)Aptr[t];
            int r = arow_b + t * 32;
            As[0][acol + 0][r] = a.x;
            As[0][acol + 1][r] = a.y;
            As[0][acol + 2][r] = a.z;
            As[0][acol + 3][r] = a.w;
            float4 w = *(const float4*)Wp[t];
            store_b(0, t, w);
        }
        __syncthreads();
    }

    for (int k0 = 0; k0 < HH; k0 += 16) {
        int cur = (k0 >> 4) & 1;
        int nxt = cur ^ 1;
        bool more = (k0 + 16 < HH);

        float4 pa[4], pw[4];
        if (more) {
            #pragma unroll
            for (int t = 0; t < 4; t++) {
                pa[t] = *(const float4*)(Aptr[t] + k0 + 16);
                pw[t] = *(const float4*)(Wp[t] + (long)(k0 + 16) * HH);
            }
        }

        #pragma unroll
        for (int kk = 0; kk < 16; kk++) {
            u64 a2[8];
            *(float4*)&a2[0] = *(float4*)&As[cur][kk][ty * 16];
            *(float4*)&a2[2] = *(float4*)&As[cur][kk][ty * 16 + 4];
            *(float4*)&a2[4] = *(float4*)&As[cur][kk][ty * 16 + 8];
            *(float4*)&a2[6] = *(float4*)&As[cur][kk][ty * 16 + 12];
            const float* brow = &Bs[cur][kk][0];
            u64 b2[8];
            *(float4*)&b2[0] = *(const float4*)(brow + co[0]);
            *(float4*)&b2[2] = *(const float4*)(brow + co[1]);
            *(float4*)&b2[4] = *(const float4*)(brow + co[2]);
            *(float4*)&b2[6] = *(const float4*)(brow + co[3]);
            #pragma unroll
            for (int i2 = 0; i2 < 8; i2++)
                #pragma unroll
                for (int j = 0; j < 8; j++)
                    fma2(acc2[i2][j], a2[i2], b2[j]);
        }

        if (more) {
            #pragma unroll
            for (int t = 0; t < 4; t++) {
                int r = arow_b + t * 32;
                As[nxt][acol + 0][r] = pa[t].x;
                As[nxt][acol + 1][r] = pa[t].y;
                As[nxt][acol + 2][r] = pa[t].z;
                As[nxt][acol + 3][r] = pa[t].w;
                store_b(nxt, t, pw[t]);
            }
            __syncthreads();
        }
    }

    // ---- epilogue: acc2[i2][j] lo->row 2*i2, hi->row 2*i2+1 ----
    // b2[j] held (b_n, b_n) with n = tx*8 + j  (chunk j>>1 gives pairs in order)
    #pragma unroll
    for (int i2 = 0; i2 < 8; i2++) {
        #pragma unroll
        for (int half = 0; half < 2; half++) {
            int m = bm + ty * 16 + 2 * i2 + half;
            const float* rrow = RESID ? (xrow(word, ent, m) + bn) : nullptr;
            #pragma unroll
            for (int j0 = 0; j0 < 8; j0 += 4) {
                int n = bn + tx * 8 + j0;
                float4 bi = *(const float4*)&bias[n];
                float4 o;
                float2 t0 = *(float2*)&acc2[i2][j0 + 0];
                float2 t1 = *(float2*)&acc2[i2][j0 + 1];
                float2 t2 = *(float2*)&acc2[i2][j0 + 2];
                float2 t3 = *(float2*)&acc2[i2][j0 + 3];
                o.x = (half ? t0.y : t0.x) + bi.x;
                o.y = (half ? t1.y : t1.x) + bi.y;
                o.z = (half ? t2.y : t2.x) + bi.z;
                o.w = (half ? t3.y : t3.x) + bi.w;
                if (RESID) {
                    float4 r = *(const float4*)&rrow[tx * 8 + j0];
                    o.x += r.x; o.y += r.y; o.z += r.z; o.w += r.w;
                }
                *(float4*)&C[(long)m * HH + n] = o;
            }
        }
    }
}

// ================= flash-style attention (R14 proven: no-max, MUFU exp) =====
#define NCHK (SS / 64)   // 9
#define ATT_SMEM ((64*68 + 2*64*68 + 2*64*68 + 64*68 + SS) * 4)

__global__ __launch_bounds__(256)
void flash_attn_kernel(const float* __restrict__ mask) {
    extern __shared__ float sm[];
    float (*qs)[68]  = (float(*)[68])sm;
    float (*ks)[68]  = qs + 64;
    float (*vs)[68]  = ks + 128;
    float (*pst)[68] = vs + 128;
    float* msm       = (float*)(pst + 64);

    int idx = blockIdx.x;
    int qt = idx % NCHK;  idx /= NCHK;
    int h  = idx % NHEAD;
    int b  = idx / NHEAD;
    int q0 = qt * 64;

    int tid = threadIdx.x;
    int qg = tid >> 4;
    int jg = tid & 15;

    const float* qb = g_q + (long)b * SS * HH + h * HD;
    const float* kb = g_k + (long)b * SS * HH + h * HD;
    const float* vb = g_v + (long)b * SS * HH + h * HD;

    for (int i = tid; i < SS; i += 256) msm[i] = mask[b * SS + i];
    #pragma unroll
    for (int t = 0; t < 4; t++) {
        int e = tid + t * 256;
        int r = e >> 4, c = e & 15;
        *(float4*)&qs[r][c * 4] = *(const float4*)&qb[(long)(q0 + r) * HH + c * 4];
    }

    #pragma unroll
    for (int t = 0; t < 4; t++) {
        int e = tid + t * 256;
        int r = e >> 4, c = e & 15;
        cp_async16(smem_u32(&ks[r][c * 4]), kb + (long)r * HH + c * 4);
        cp_async16(smem_u32(&vs[r][c * 4]), vb + (long)r * HH + c * 4);
    }
    CP_COMMIT();

    float l[4];
    u64 acc2[4][2];
    #pragma unroll
    for (int i = 0; i < 4; i++) {
        l[i] = 0.f;
        acc2[i][0] = 0ULL; acc2[i][1] = 0ULL;
    }

    for (int c = 0; c < NCHK; c++) {
        int buf = c & 1;
        if (c + 1 < NCHK) {
            int nb_ = buf ^ 1;
            long rbase = (long)(c + 1) * 64;
            #pragma unroll
            for (int t = 0; t < 4; t++) {
                int e = tid + t * 256;
                int r = e >> 4, cc = e & 15;
                cp_async16(smem_u32(&ks[nb_ * 64 + r][cc * 4]),
                           kb + (rbase + r) * HH + cc * 4);
                cp_async16(smem_u32(&vs[nb_ * 64 + r][cc * 4]),
                           vb + (rbase + r) * HH + cc * 4);
            }
            CP_COMMIT();
            CP_WAIT1();
        } else {
            CP_WAIT0();
        }
        __syncthreads();

        // ---- scores via packed f32x2 along d ----
        u64 s2[4][4];
        #pragma unroll
        for (int i = 0; i < 4; i++)
            #pragma unroll
            for (int j = 0; j < 4; j++) s2[i][j] = 0ULL;

        #pragma unroll
        for (int d4 = 0; d4 < 16; d4++) {
            u64 q2[4][2];
            #pragma unroll
            for (int iq = 0; iq < 4; iq++)
                *(float4*)&q2[iq][0] = *(float4*)&qs[4 * qg + iq][d4 * 4];
            #pragma unroll
            for (int ij = 0; ij < 4; ij++) {
                u64 k2[2];
                *(float4*)&k2[0] = *(float4*)&ks[buf * 64 + jg + 16 * ij][d4 * 4];
                #pragma unroll
                for (int iq = 0; iq < 4; iq++) {
                    fma2(s2[iq][ij], q2[iq][0], k2[0]);
                    fma2(s2[iq][ij], q2[iq][1], k2[1]);
                }
            }
        }

        // ---- probs: p = exp(s/8 + mask) on MUFU; local l accumulation ----
        float p[4][4];
        #pragma unroll
        for (int ij = 0; ij < 4; ij++) {
            float mk = msm[c * 64 + jg + 16 * ij];
            #pragma unroll
            for (int iq = 0; iq < 4; iq++) {
                float2 f = *(float2*)&s2[iq][ij];
                float v = fmaf(f.x + f.y, 0.125f, mk);
                float e = __expf(v);
                p[iq][ij] = e;
                l[iq] += e;
            }
        }

        #pragma unroll
        for (int ij = 0; ij < 4; ij++) {
            float4 pv = make_float4(p[0][ij], p[1][ij], p[2][ij], p[3][ij]);
            *(float4*)&pst[jg + 16 * ij][4 * qg] = pv;
        }
        __syncthreads();

        // ---- ctx accumulation (unnormalized probs) ----
        #pragma unroll 4
        for (int j = 0; j < 64; j++) {
            float4 pv = *(float4*)&pst[j][4 * qg];
            u64 v2[2];
            *(float4*)&v2[0] = *(float4*)&vs[buf * 64 + j][jg * 4];
            u64 p0 = pack2(pv.x, pv.x);
            u64 p1 = pack2(pv.y, pv.y);
            u64 p2 = pack2(pv.z, pv.z);
            u64 p3 = pack2(pv.w, pv.w);
            fma2(acc2[0][0], p0, v2[0]); fma2(acc2[0][1], p0, v2[1]);
            fma2(acc2[1][0], p1, v2[0]); fma2(acc2[1][1], p1, v2[1]);
            fma2(acc2[2][0], p2, v2[0]); fma2(acc2[2][1], p2, v2[1]);
            fma2(acc2[3][0], p3, v2[0]); fma2(acc2[3][1], p3, v2[1]);
        }
        __syncthreads();
    }

    // ---- single deferred l reduction across the 16 jg lanes ----
    #pragma unroll
    for (int iq = 0; iq < 4; iq++) {
        #pragma unroll
        for (int o = 1; o < 16; o <<= 1)
            l[iq] += __shfl_xor_sync(0xffffffff, l[iq], o);
    }

    #pragma unroll
    for (int iq = 0; iq < 4; iq++) {
        float inv = 1.0f / l[iq];
        float4 av = *(float4*)&acc2[iq][0];
        float4 o;
        o.x = av.x * inv; o.y = av.y * inv;
        o.z = av.z * inv; o.w = av.w * inv;
        long row = (long)b * SS + q0 + 4 * qg + iq;
        *(float4*)&g_ctx[row * HH + h * HD + jg * 4] = o;
    }
}

// ---------------- LayerNorm + output split ordering ----------------
__global__ __launch_bounds__(256)
void ln_out_kernel(const float* __restrict__ ln_w, const float* __restrict__ ln_b,
                   float* __restrict__ out) {
    int row = blockIdx.x;
    int b = row / SS, s = row % SS;
    const float* y = g_y + (long)row * HH;
    int tid = threadIdx.x;

    float4 v = *(const float4*)&y[tid * 4];
    float sum = v.x + v.y + v.z + v.w;
    float sq  = v.x * v.x + v.y * v.y + v.z * v.z + v.w * v.w;

    __shared__ float s_sum[8], s_sq[8], s_stats[2];
    int w = tid / 32, lane = tid % 32;
    #pragma unroll
    for (int o = 16; o > 0; o >>= 1) {
        sum += __shfl_xor_sync(0xffffffff, sum, o);
        sq  += __shfl_xor_sync(0xffffffff, sq,  o);
    }
    if (lane == 0) { s_sum[w] = sum; s_sq[w] = sq; }
    __syncthreads();
    if (tid == 0) {
        float ts = 0.f, tq = 0.f;
        #pragma unroll
        for (int i = 0; i < 8; i++) { ts += s_sum[i]; tq += s_sq[i]; }
        float mean = ts * (1.0f / HH);
        float var  = tq * (1.0f / HH) - mean * mean;
        s_stats[0] = mean;
        s_stats[1] = rsqrtf(var + 1e-12f);
    }
    __syncthreads();
    float mean = s_stats[0], inv = s_stats[1];

    long dst;
    if (s < LW) dst = ((long)b * LW + s) * HH;
    else        dst = (long)NB * LW * HH + ((long)b * LE + (s - LW)) * HH;

    float4 w4 = *(const float4*)&ln_w[tid * 4];
    float4 b4 = *(const float4*)&ln_b[tid * 4];
    float4 o;
    o.x = (v.x - mean) * inv * w4.x + b4.x;
    o.y = (v.y - mean) * inv * w4.y + b4.y;
    o.z = (v.z - mean) * inv * w4.z + b4.z;
    o.w = (v.w - mean) * inv * w4.w + b4.w;
    *(float4*)&out[dst + tid * 4] = o;
}

// ---------------- launch ----------------
extern "C" void kernel_launch(void* const* d_in, const int* in_sizes, int n_in,
                              void* d_out, int out_size) {
    const float* word = (const float*)d_in[0];
    const float* ent  = (const float*)d_in[1];
    const float* mask = (const float*)d_in[2];
    const float* Wq   = (const float*)d_in[3];
    const float* bq   = (const float*)d_in[4];
    const float* Wk   = (const float*)d_in[5];
    const float* bk   = (const float*)d_in[6];
    const float* Wv   = (const float*)d_in[7];
    const float* bv   = (const float*)d_in[8];
    const float* Wo   = (const float*)d_in[9];
    const float* bo   = (const float*)d_in[10];
    const float* lnw  = (const float*)d_in[11];
    const float* lnb  = (const float*)d_in[12];
    float* out = (float*)d_out;

    float *pq, *pk, *pv, *pc, *py;
    cudaGetSymbolAddress((void**)&pq, g_q);
    cudaGetSymbolAddress((void**)&pk, g_k);
    cudaGetSymbolAddress((void**)&pv, g_v);
    cudaGetSymbolAddress((void**)&pc, g_ctx);
    cudaGetSymbolAddress((void**)&py, g_y);

    cudaFuncSetAttribute(flash_attn_kernel,
                         cudaFuncAttributeMaxDynamicSharedMemorySize, ATT_SMEM);

    // 1) Q/K/V projections: ONE launch, grid.z selects the weight set
    {
        dim3 grid(HH / 128, MTOT / 128, 3);
        gemm_kernel<false, true><<<grid, 128>>>(
            nullptr, word, ent,
            Wq, Wk, Wv, bq, bk, bv, pq, pk, pv);
    }

    // 2) flash attention (no-max softmax, MUFU exp)
    flash_attn_kernel<<<NB * NHEAD * NCHK, 256, ATT_SMEM>>>(mask);

    // 3) output projection + bias + residual (residual = virtual concat)
    {
        dim3 grid(HH / 128, MTOT / 128, 1);
        gemm_kernel<true, false><<<grid, 128>>>(
            pc, word, ent,
            Wo, Wo, Wo, bo, bo, bo, py, py, py);
    }

    // 4) LayerNorm + split write
    ln_out_kernel<<<MTOT, 256>>>(lnw, lnb, out);
}

// round 16
// speedup vs baseline: 1.1398x; 1.1398x over previous
#include <cuda_runtime.h>
#include <math.h>
#include <stdint.h>

#define NB 8
#define LW 512
#define LE 64
#define SS 576
#define HH 1024
#define NHEAD 16
#define HD 64
#define MTOT (NB*SS)      // 4608

typedef unsigned long long u64;

// ---------------- scratch (device globals; no allocation) ----------------
__device__ float g_q  [ (long)MTOT * HH ];
__device__ float g_k  [ (long)MTOT * HH ];
__device__ float g_v  [ (long)MTOT * HH ];
__device__ float g_ctx[ (long)MTOT * HH ];
__device__ float g_y  [ (long)MTOT * HH ];

// ---------------- packed f32x2 helpers ----------------
__device__ __forceinline__ u64 pack2(float lo, float hi) {
    u64 r; asm("mov.b64 %0, {%1, %2};" : "=l"(r) : "f"(lo), "f"(hi)); return r;
}
__device__ __forceinline__ void fma2(u64& d, u64 a, u64 b) {
    asm("fma.rn.f32x2 %0, %1, %2, %0;" : "+l"(d) : "l"(a), "l"(b));
}

__device__ __forceinline__ uint32_t smem_u32(const void* p) {
    uint32_t a;
    asm("{ .reg .u64 t; cvta.to.shared.u64 t, %1; cvt.u32.u64 %0, t; }" : "=r"(a) : "l"(p));
    return a;
}
__device__ __forceinline__ void cp_async16(uint32_t dst, const void* src) {
    asm volatile("cp.async.cg.shared.global [%0], [%1], 16;" :: "r"(dst), "l"(src));
}
#define CP_COMMIT() asm volatile("cp.async.commit_group;" ::: "memory")
#define CP_WAIT1()  asm volatile("cp.async.wait_group 1;" ::: "memory")
#define CP_WAIT0()  asm volatile("cp.async.wait_group 0;" ::: "memory")

// row m of virtual concat([B,Lw,H] word, [B,Le,H] ent)
__device__ __forceinline__ const float* xrow(const float* __restrict__ word,
                                             const float* __restrict__ ent, int m) {
    int b = m / SS, s = m % SS;
    return (s < LW) ? word + ((long)b * LW + s) * HH
                    : ent  + ((long)b * LE + (s - LW)) * HH;
}

// ------------- software-pipelined fp32 GEMM (R12/R14 proven config) ---------
template<bool RESID, bool CONCAT_A>
__global__ __launch_bounds__(128)
void gemm_kernel(const float* __restrict__ Adirect,
                 const float* __restrict__ word,
                 const float* __restrict__ ent,
                 const float* __restrict__ W0,
                 const float* __restrict__ W1,
                 const float* __restrict__ W2,
                 const float* __restrict__ b0,
                 const float* __restrict__ b1,
                 const float* __restrict__ b2,
                 float* __restrict__ C0,
                 float* __restrict__ C1,
                 float* __restrict__ C2) {
    __shared__ float As[2][16][132];
    __shared__ float Bs[2][16][128];

    int z = blockIdx.z;
    const float* W    = (z == 0) ? W0 : (z == 1) ? W1 : W2;
    const float* bias = (z == 0) ? b0 : (z == 1) ? b1 : b2;
    float*       C    = (z == 0) ? C0 : (z == 1) ? C1 : C2;

    int tid = threadIdx.x;
    int bm = blockIdx.y * 128;
    int bn = blockIdx.x * 128;
    int ty = tid >> 4;
    int tx = tid & 15;

    u64 acc2[8][8];
    #pragma unroll
    for (int i = 0; i < 8; i++)
        #pragma unroll
        for (int j = 0; j < 8; j++) acc2[i][j] = 0ULL;

    int arow_b = tid >> 2;
    int acol   = (tid & 3) * 4;
    const float* Aptr[4];
    #pragma unroll
    for (int t = 0; t < 4; t++) {
        int m = bm + arow_b + t * 32;
        Aptr[t] = (CONCAT_A ? xrow(word, ent, m)
                            : Adirect + (long)m * HH) + acol;
    }

    const float* Wp[4];
    uint32_t bdst[2][4];
    #pragma unroll
    for (int t = 0; t < 4; t++) {
        int idx = tid + t * 128;
        int br = idx >> 5, bc = (idx & 31) * 4;
        Wp[t] = W + (long)br * HH + bn + bc;
        bdst[0][t] = smem_u32(&Bs[0][br][bc]);
        bdst[1][t] = smem_u32(&Bs[1][br][bc]);
    }

    {
        #pragma unroll
        for (int t = 0; t < 4; t++) {
            float4 a = *(const float4*)Aptr[t];
            int r = arow_b + t * 32;
            As[0][acol + 0][r] = a.x;
            As[0][acol + 1][r] = a.y;
            As[0][acol + 2][r] = a.z;
            As[0][acol + 3][r] = a.w;
            cp_async16(bdst[0][t], Wp[t]);
        }
        CP_COMMIT();
        CP_WAIT0();
        __syncthreads();
    }

    for (int k0 = 0; k0 < HH; k0 += 16) {
        int cur = (k0 >> 4) & 1;
        int nxt = cur ^ 1;
        bool more = (k0 + 16 < HH);

        float4 pa[4];
        if (more) {
            #pragma unroll
            for (int t = 0; t < 4; t++) {
                pa[t] = *(const float4*)(Aptr[t] + k0 + 16);
                cp_async16(bdst[nxt][t], Wp[t] + (long)(k0 + 16) * HH);
            }
            CP_COMMIT();
        }

        #pragma unroll
        for (int kk = 0; kk < 16; kk++) {
            u64 a2[8];
            *(float4*)&a2[0] = *(float4*)&As[cur][kk][ty * 16];
            *(float4*)&a2[2] = *(float4*)&As[cur][kk][ty * 16 + 4];
            *(float4*)&a2[4] = *(float4*)&As[cur][kk][ty * 16 + 8];
            *(float4*)&a2[6] = *(float4*)&As[cur][kk][ty * 16 + 12];
            float b[8];
            *(float4*)&b[0] = *(float4*)&Bs[cur][kk][tx * 8];
            *(float4*)&b[4] = *(float4*)&Bs[cur][kk][tx * 8 + 4];
            u64 b2[8];
            #pragma unroll
            for (int j = 0; j < 8; j++) b2[j] = pack2(b[j], b[j]);
            #pragma unroll
            for (int i2 = 0; i2 < 8; i2++)
                #pragma unroll
                for (int j = 0; j < 8; j++)
                    fma2(acc2[i2][j], a2[i2], b2[j]);
        }

        if (more) {
            #pragma unroll
            for (int t = 0; t < 4; t++) {
                int r = arow_b + t * 32;
                As[nxt][acol + 0][r] = pa[t].x;
                As[nxt][acol + 1][r] = pa[t].y;
                As[nxt][acol + 2][r] = pa[t].z;
                As[nxt][acol + 3][r] = pa[t].w;
            }
            CP_WAIT0();
            __syncthreads();
        }
    }

    #pragma unroll
    for (int i2 = 0; i2 < 8; i2++) {
        #pragma unroll
        for (int half = 0; half < 2; half++) {
            int m = bm + ty * 16 + 2 * i2 + half;
            const float* rrow = RESID ? (xrow(word, ent, m) + bn) : nullptr;
            #pragma unroll
            for (int j0 = 0; j0 < 8; j0 += 4) {
                int n = bn + tx * 8 + j0;
                float4 bi = *(const float4*)&bias[n];
                float4 o;
                float2 t0 = *(float2*)&acc2[i2][j0 + 0];
                float2 t1 = *(float2*)&acc2[i2][j0 + 1];
                float2 t2 = *(float2*)&acc2[i2][j0 + 2];
                float2 t3 = *(float2*)&acc2[i2][j0 + 3];
                o.x = (half ? t0.y : t0.x) + bi.x;
                o.y = (half ? t1.y : t1.x) + bi.y;
                o.z = (half ? t2.y : t2.x) + bi.z;
                o.w = (half ? t3.y : t3.x) + bi.w;
                if (RESID) {
                    float4 r = *(const float4*)&rrow[tx * 8 + j0];
                    o.x += r.x; o.y += r.y; o.z += r.z; o.w += r.w;
                }
                *(float4*)&C[(long)m * HH + n] = o;
            }
        }
    }
}

// ======== flash attention: 3 CTAs/SM, single-buffered K/V, split waits ======
// smem: qs + ks + vs + pst (each 64x68) + msm[576] = 70.3 KB
// Schedule per chunk c:
//   WAIT0(K(c)) ; barrier ; commit V(c) [c>=1]        <- V flies over scores
//   scores(ks) ; probs ; pst write ; barrier
//   commit K(c+1) ; WAIT1(V(c)) ; barrier ; ctx(vs,pst)
#define NCHK (SS / 64)   // 9
#define ATT_SMEM ((4*64*68 + SS) * 4)

__global__ __launch_bounds__(256, 3)
void flash_attn_kernel(const float* __restrict__ mask) {
    extern __shared__ float sm[];
    float (*qs)[68]  = (float(*)[68])sm;
    float (*ks)[68]  = qs + 64;
    float (*vs)[68]  = ks + 64;
    float (*pst)[68] = vs + 64;
    float* msm       = (float*)(pst + 64);

    int idx = blockIdx.x;
    int qt = idx % NCHK;  idx /= NCHK;
    int h  = idx % NHEAD;
    int b  = idx / NHEAD;
    int q0 = qt * 64;

    int tid = threadIdx.x;
    int qg = tid >> 4;
    int jg = tid & 15;

    const float* qb = g_q + (long)b * SS * HH + h * HD;
    const float* kb = g_k + (long)b * SS * HH + h * HD;
    const float* vb = g_v + (long)b * SS * HH + h * HD;

    int lr[4], lc[4];
    #pragma unroll
    for (int t = 0; t < 4; t++) {
        int e = tid + t * 256;
        lr[t] = e >> 4; lc[t] = (e & 15) * 4;
    }

    for (int i = tid; i < SS; i += 256) msm[i] = mask[b * SS + i];
    #pragma unroll
    for (int t = 0; t < 4; t++)
        *(float4*)&qs[lr[t]][lc[t]] = *(const float4*)&qb[(long)(q0 + lr[t]) * HH + lc[t]];

    // prologue: K0 + V0 (one group)
    #pragma unroll
    for (int t = 0; t < 4; t++) {
        cp_async16(smem_u32(&ks[lr[t]][lc[t]]), kb + (long)lr[t] * HH + lc[t]);
        cp_async16(smem_u32(&vs[lr[t]][lc[t]]), vb + (long)lr[t] * HH + lc[t]);
    }
    CP_COMMIT();

    float l[4];
    u64 acc2[4][2];
    #pragma unroll
    for (int i = 0; i < 4; i++) {
        l[i] = 0.f;
        acc2[i][0] = 0ULL; acc2[i][1] = 0ULL;
    }

    for (int c = 0; c < NCHK; c++) {
        // K(c) ready (everything committed so far done)
        CP_WAIT0();
        __syncthreads();

        // launch V(c) for c>=1 (vs free: ctx(c-1) finished before barrier)
        if (c >= 1) {
            long rbase = (long)c * 64;
            #pragma unroll
            for (int t = 0; t < 4; t++)
                cp_async16(smem_u32(&vs[lr[t]][lc[t]]),
                           vb + (rbase + lr[t]) * HH + lc[t]);
            CP_COMMIT();
        }

        // ---- scores via packed f32x2 along d ----
        u64 s2[4][4];
        #pragma unroll
        for (int i = 0; i < 4; i++)
            #pragma unroll
            for (int j = 0; j < 4; j++) s2[i][j] = 0ULL;

        #pragma unroll
        for (int d4 = 0; d4 < 16; d4++) {
            u64 q2[4][2];
            #pragma unroll
            for (int iq = 0; iq < 4; iq++)
                *(float4*)&q2[iq][0] = *(float4*)&qs[4 * qg + iq][d4 * 4];
            #pragma unroll
            for (int ij = 0; ij < 4; ij++) {
                u64 k2[2];
                *(float4*)&k2[0] = *(float4*)&ks[jg + 16 * ij][d4 * 4];
                #pragma unroll
                for (int iq = 0; iq < 4; iq++) {
                    fma2(s2[iq][ij], q2[iq][0], k2[0]);
                    fma2(s2[iq][ij], q2[iq][1], k2[1]);
                }
            }
        }

        // ---- probs (MUFU exp, no-max softmax) ----
        float p[4][4];
        #pragma unroll
        for (int ij = 0; ij < 4; ij++) {
            float mk = msm[c * 64 + jg + 16 * ij];
            #pragma unroll
            for (int iq = 0; iq < 4; iq++) {
                float2 f = *(float2*)&s2[iq][ij];
                float v = fmaf(f.x + f.y, 0.125f, mk);
                float e = __expf(v);
                p[iq][ij] = e;
                l[iq] += e;
            }
        }

        #pragma unroll
        for (int ij = 0; ij < 4; ij++) {
            float4 pv = make_float4(p[0][ij], p[1][ij], p[2][ij], p[3][ij]);
            *(float4*)&pst[jg + 16 * ij][4 * qg] = pv;
        }
        __syncthreads();   // scores done reading ks; pst visible

        // launch K(c+1) (ks free now)
        if (c + 1 < NCHK) {
            long rbase = (long)(c + 1) * 64;
            #pragma unroll
            for (int t = 0; t < 4; t++)
                cp_async16(smem_u32(&ks[lr[t]][lc[t]]),
                           kb + (rbase + lr[t]) * HH + lc[t]);
            CP_COMMIT();
        }

        // V(c) must be complete before ctx; allow K(c+1) outstanding
        if (c + 1 < NCHK) { CP_WAIT1(); } else { CP_WAIT0(); }
        __syncthreads();

        // ---- ctx accumulation ----
        #pragma unroll 4
        for (int j = 0; j < 64; j++) {
            float4 pv = *(float4*)&pst[j][4 * qg];
            u64 v2[2];
            *(float4*)&v2[0] = *(float4*)&vs[j][jg * 4];
            u64 p0 = pack2(pv.x, pv.x);
            u64 p1 = pack2(pv.y, pv.y);
            u64 p2 = pack2(pv.z, pv.z);
            u64 p3 = pack2(pv.w, pv.w);
            fma2(acc2[0][0], p0, v2[0]); fma2(acc2[0][1], p0, v2[1]);
            fma2(acc2[1][0], p1, v2[0]); fma2(acc2[1][1], p1, v2[1]);
            fma2(acc2[2][0], p2, v2[0]); fma2(acc2[2][1], p2, v2[1]);
            fma2(acc2[3][0], p3, v2[0]); fma2(acc2[3][1], p3, v2[1]);
        }
        // next loop-top barrier protects vs/pst reuse
    }

    // ---- single deferred l reduction across the 16 jg lanes ----
    #pragma unroll
    for (int iq = 0; iq < 4; iq++) {
        #pragma unroll
        for (int o = 1; o < 16; o <<= 1)
            l[iq] += __shfl_xor_sync(0xffffffff, l[iq], o);
    }

    #pragma unroll
    for (int iq = 0; iq < 4; iq++) {
        float inv = 1.0f / l[iq];
        float4 av = *(float4*)&acc2[iq][0];
        float4 o;
        o.x = av.x * inv; o.y = av.y * inv;
        o.z = av.z * inv; o.w = av.w * inv;
        long row = (long)b * SS + q0 + 4 * qg + iq;
        *(float4*)&g_ctx[row * HH + h * HD + jg * 4] = o;
    }
}

// ---------------- LayerNorm + output split ordering ----------------
__global__ __launch_bounds__(256)
void ln_out_kernel(const float* __restrict__ ln_w, const float* __restrict__ ln_b,
                   float* __restrict__ out) {
    int row = blockIdx.x;
    int b = row / SS, s = row % SS;
    const float* y = g_y + (long)row * HH;
    int tid = threadIdx.x;

    float4 v = *(const float4*)&y[tid * 4];
    float sum = v.x + v.y + v.z + v.w;
    float sq  = v.x * v.x + v.y * v.y + v.z * v.z + v.w * v.w;

    __shared__ float s_sum[8], s_sq[8], s_stats[2];
    int w = tid / 32, lane = tid % 32;
    #pragma unroll
    for (int o = 16; o > 0; o >>= 1) {
        sum += __shfl_xor_sync(0xffffffff, sum, o);
        sq  += __shfl_xor_sync(0xffffffff, sq,  o);
    }
    if (lane == 0) { s_sum[w] = sum; s_sq[w] = sq; }
    __syncthreads();
    if (tid == 0) {
        float ts = 0.f, tq = 0.f;
        #pragma unroll
        for (int i = 0; i < 8; i++) { ts += s_sum[i]; tq += s_sq[i]; }
        float mean = ts * (1.0f / HH);
        float var  = tq * (1.0f / HH) - mean * mean;
        s_stats[0] = mean;
        s_stats[1] = rsqrtf(var + 1e-12f);
    }
    __syncthreads();
    float mean = s_stats[0], inv = s_stats[1];

    long dst;
    if (s < LW) dst = ((long)b * LW + s) * HH;
    else        dst = (long)NB * LW * HH + ((long)b * LE + (s - LW)) * HH;

    float4 w4 = *(const float4*)&ln_w[tid * 4];
    float4 b4 = *(const float4*)&ln_b[tid * 4];
    float4 o;
    o.x = (v.x - mean) * inv * w4.x + b4.x;
    o.y = (v.y - mean) * inv * w4.y + b4.y;
    o.z = (v.z - mean) * inv * w4.z + b4.z;
    o.w = (v.w - mean) * inv * w4.w + b4.w;
    *(float4*)&out[dst + tid * 4] = o;
}

// ---------------- launch ----------------
extern "C" void kernel_launch(void* const* d_in, const int* in_sizes, int n_in,
                              void* d_out, int out_size) {
    const float* word = (const float*)d_in[0];
    const float* ent  = (const float*)d_in[1];
    const float* mask = (const float*)d_in[2];
    const float* Wq   = (const float*)d_in[3];
    const float* bq   = (const float*)d_in[4];
    const float* Wk   = (const float*)d_in[5];
    const float* bk   = (const float*)d_in[6];
    const float* Wv   = (const float*)d_in[7];
    const float* bv   = (const float*)d_in[8];
    const float* Wo   = (const float*)d_in[9];
    const float* bo   = (const float*)d_in[10];
    const float* lnw  = (const float*)d_in[11];
    const float* lnb  = (const float*)d_in[12];
    float* out = (float*)d_out;

    float *pq, *pk, *pv, *pc, *py;
    cudaGetSymbolAddress((void**)&pq, g_q);
    cudaGetSymbolAddress((void**)&pk, g_k);
    cudaGetSymbolAddress((void**)&pv, g_v);
    cudaGetSymbolAddress((void**)&pc, g_ctx);
    cudaGetSymbolAddress((void**)&py, g_y);

    cudaFuncSetAttribute(flash_attn_kernel,
                         cudaFuncAttributeMaxDynamicSharedMemorySize, ATT_SMEM);

    // 1) Q/K/V projections: ONE launch, grid.z selects the weight set
    {
        dim3 grid(HH / 128, MTOT / 128, 3);
        gemm_kernel<false, true><<<grid, 128>>>(
            nullptr, word, ent,
            Wq, Wk, Wv, bq, bk, bv, pq, pk, pv);
    }

    // 2) flash attention (3 CTAs/SM, split-wait single buffers)
    flash_attn_kernel<<<NB * NHEAD * NCHK, 256, ATT_SMEM>>>(mask);

    // 3) output projection + bias + residual (residual = virtual concat)
    {
        dim3 grid(HH / 128, MTOT / 128, 1);
        gemm_kernel<true, false><<<grid, 128>>>(
            pc, word, ent,
            Wo, Wo, Wo, bo, bo, bo, py, py, py);
    }

    // 4) LayerNorm + split write
    ln_out_kernel<<<MTOT, 256>>>(lnw, lnb, out);
}